// round 2
// baseline (speedup 1.0000x reference)
#include <cuda_runtime.h>
#include <math.h>

#define CH 512
#define P 8
#define NG 64
#define N_SAMP 16
#define H 64
#define W 64
#define HW 4096

__device__ float g_d[N_SAMP * 72];      // leaky(d)[n, j, ky, kx]
__device__ float g_S[N_SAMP];           // sum_j pk[n,j]
__device__ float g_bias[N_SAMP * CH];
__device__ float g_mean[N_SAMP * CH];
__device__ float g_rstd[N_SAMP * CH];

// ---------------------------------------------------------------------------
// Kernel A: per-sample style processing. 16 blocks x 512 threads.
// ---------------------------------------------------------------------------
__global__ void __launch_bounds__(512) prep_kernel(
    const float* __restrict__ style,   // [16,512,4,4]
    const float* __restrict__ dw_w,    // [8,512,2,2]
    const float* __restrict__ dw_b,    // [8]
    const float* __restrict__ pk_w,    // [8,512]
    const float* __restrict__ pk_b,    // [8]
    const float* __restrict__ pb_w,    // [512,512]
    const float* __restrict__ pb_b)    // [512]
{
    int n = blockIdx.x;
    __shared__ float st[512 * 16];   // style map for this sample (32 KB)
    __shared__ float sd[512];        // spatial mean per channel
    __shared__ float red[288];
    int tid = threadIdx.x;

    const float* sp = style + (size_t)n * 512 * 16;
    for (int i = tid; i < 512 * 16; i += 512) st[i] = sp[i];
    __syncthreads();

    // s_d[c] = mean over 4x4
    {
        float a = 0.f;
        #pragma unroll
        for (int p = 0; p < 16; p++) a += st[tid * 16 + p];
        sd[tid] = a * (1.f / 16.f);
    }
    __syncthreads();

    // d[j,ky,kx]: 2x2 valid conv over 512 channels. 72 outputs x 4 partials.
    if (tid < 288) {
        int outi = tid >> 2;
        int part = tid & 3;
        int j  = outi / 9;
        int pos = outi % 9;
        int ky = pos / 3, kx = pos % 3;
        float acc = 0.f;
        const float* wv = dw_w + (size_t)j * 512 * 4;
        for (int c = part * 128; c < part * 128 + 128; c++) {
            const float* stc = st + c * 16 + ky * 4 + kx;
            const float* wc  = wv + c * 4;
            acc += wc[0] * stc[0] + wc[1] * stc[1]
                 + wc[2] * stc[4] + wc[3] * stc[5];
        }
        red[tid] = acc;
    }
    __syncthreads();
    if (tid < 72) {
        int j = tid / 9;
        float v = red[tid * 4] + red[tid * 4 + 1] + red[tid * 4 + 2] + red[tid * 4 + 3]
                + dw_b[j];
        g_d[n * 72 + tid] = v >= 0.f ? v : 0.01f * v;   // leaky
    }

    int warp = tid >> 5, lane = tid & 31;

    // bias[c] = <s_d, pb_w[c,:]> + pb_b[c]   — 16 warps x 32 outputs, coalesced rows
    for (int i = 0; i < 32; i++) {
        int c = warp + i * 16;
        float acc = 0.f;
        const float* row = pb_w + (size_t)c * 512;
        #pragma unroll
        for (int k = 0; k < 16; k++) {
            int cc = lane + k * 32;
            acc += sd[cc] * row[cc];
        }
        #pragma unroll
        for (int off = 16; off; off >>= 1)
            acc += __shfl_down_sync(0xffffffffu, acc, off);
        if (lane == 0) g_bias[n * 512 + c] = acc + pb_b[c];
    }

    // S = sum_j ( <s_d, pk_w[j,:]> + pk_b[j] )
    if (warp == 0) {
        float acc = 0.f;
        #pragma unroll
        for (int k = 0; k < 16; k++) {
            int c = lane + k * 32;
            float wsum = 0.f;
            #pragma unroll
            for (int j = 0; j < 8; j++) wsum += pk_w[j * 512 + c];
            acc += sd[c] * wsum;
        }
        #pragma unroll
        for (int off = 16; off; off >>= 1)
            acc += __shfl_down_sync(0xffffffffu, acc, off);
        if (lane == 0) {
            float bsum = 0.f;
            #pragma unroll
            for (int j = 0; j < 8; j++) bsum += pk_b[j];
            g_S[n] = acc + bsum;
        }
    }
}

// ---------------------------------------------------------------------------
// Kernel B: instance-norm stats per (n,c). 8192 blocks x 256 threads.
// ---------------------------------------------------------------------------
__global__ void __launch_bounds__(256) stats_kernel(const float* __restrict__ content)
{
    int ch = blockIdx.x;                  // n*512 + c
    const float* p = content + (size_t)ch * HW;
    float sum = 0.f, sq = 0.f;
    for (int i = threadIdx.x; i < HW; i += 256) {
        float v = p[i];
        sum += v;
        sq  += v * v;
    }
    __shared__ float s1[8], s2[8];
    int lane = threadIdx.x & 31, warp = threadIdx.x >> 5;
    #pragma unroll
    for (int off = 16; off; off >>= 1) {
        sum += __shfl_down_sync(0xffffffffu, sum, off);
        sq  += __shfl_down_sync(0xffffffffu, sq,  off);
    }
    if (lane == 0) { s1[warp] = sum; s2[warp] = sq; }
    __syncthreads();
    if (threadIdx.x == 0) {
        float S = 0.f, Q = 0.f;
        #pragma unroll
        for (int w = 0; w < 8; w++) { S += s1[w]; Q += s2[w]; }
        float mean = S * (1.f / HW);
        float var  = (Q - S * S * (1.f / HW)) * (1.f / (HW - 1));  // ddof=1
        g_mean[ch] = mean;
        g_rstd[ch] = rsqrtf(var + 1e-5f);
    }
}

// ---------------------------------------------------------------------------
// Kernel C: fused group conv + pointwise-collapse + instance norm + multiply.
// Grid (4 tiles, 64 groups, 16 samples) x 256 threads.
// ---------------------------------------------------------------------------
#define TILE_H 16
#define SROWS 18
#define SCOLS 66

__global__ void __launch_bounds__(256) main_kernel(
    const float* __restrict__ content, float* __restrict__ out)
{
    int tile = blockIdx.x;   // 0..3
    int g    = blockIdx.y;   // 0..63
    int n    = blockIdx.z;   // 0..15

    __shared__ float s[8][SROWS][SCOLS];  // 38016 B
    __shared__ float fd[72];
    __shared__ float fb[8], fm[8], fr[8];
    __shared__ float fS;

    int tid = threadIdx.x;
    int cbase = n * 512 + g * 8;
    if (tid < 72)       fd[tid] = g_d[n * 72 + tid];
    else if (tid < 80)  fb[tid - 72] = g_bias[cbase + tid - 72];
    else if (tid < 88)  fm[tid - 80] = g_mean[cbase + tid - 80];
    else if (tid < 96)  fr[tid - 88] = g_rstd[cbase + tid - 88];
    else if (tid == 96) fS = g_S[n];

    const float* base = content + (size_t)cbase * HW;
    int row0 = tile * TILE_H;

    // cooperative load with reflect padding (halo of 1 on all sides)
    for (int idx = tid; idx < 8 * SROWS * SCOLS; idx += 256) {
        int j   = idx / (SROWS * SCOLS);
        int rem = idx % (SROWS * SCOLS);
        int lr  = rem / SCOLS;
        int lc  = rem % SCOLS;
        int gr = row0 + lr - 1;
        gr = gr < 0 ? -gr : (gr >= H ? 2 * H - 2 - gr : gr);
        int gc = lc - 1;
        gc = gc < 0 ? -gc : (gc >= W ? 2 * W - 2 - gc : gc);
        (&s[0][0][0])[idx] = base[j * HW + gr * W + gc];
    }
    __syncthreads();

    float S = fS;
    float* obase = out + (size_t)cbase * HW;

    #pragma unroll
    for (int k = 0; k < 4; k++) {
        int p = tid + k * 256;         // 0..1023 over the 16x64 tile
        int h = p >> 6;
        int w = p & 63;

        float D = 0.f;
        #pragma unroll
        for (int j = 0; j < 8; j++)
            #pragma unroll
            for (int ky = 0; ky < 3; ky++)
                #pragma unroll
                for (int kx = 0; kx < 3; kx++)
                    D += fd[j * 9 + ky * 3 + kx] * s[j][h + ky][w + kx];

        float DS = D * S;
        float* op = obase + (row0 + h) * W + w;
        #pragma unroll
        for (int o = 0; o < 8; o++) {
            float pred = DS + fb[o];
            pred = pred >= 0.f ? pred : 0.01f * pred;
            float normv = (s[o][h + 1][w + 1] - fm[o]) * fr[o];
            op[(size_t)o * HW] = normv * pred;
        }
    }
}

// ---------------------------------------------------------------------------
extern "C" void kernel_launch(void* const* d_in, const int* in_sizes, int n_in,
                              void* d_out, int out_size)
{
    const float* style   = (const float*)d_in[0];
    const float* content = (const float*)d_in[1];
    const float* dw_w    = (const float*)d_in[2];
    const float* dw_b    = (const float*)d_in[3];
    const float* pk_w    = (const float*)d_in[4];
    const float* pk_b    = (const float*)d_in[5];
    const float* pb_w    = (const float*)d_in[6];
    const float* pb_b    = (const float*)d_in[7];
    float* out = (float*)d_out;

    prep_kernel<<<N_SAMP, 512>>>(style, dw_w, dw_b, pk_w, pk_b, pb_w, pb_b);
    stats_kernel<<<N_SAMP * CH, 256>>>(content);
    main_kernel<<<dim3(4, NG, N_SAMP), 256>>>(content, out);
}

// round 3
// speedup vs baseline: 1.4215x; 1.4215x over previous
#include <cuda_runtime.h>
#include <math.h>

#define CH 512
#define P 8
#define NG 64
#define N_SAMP 16
#define H 64
#define W 64
#define HW 4096

__device__ float g_d[N_SAMP * 72];      // leaky(d)[n, j, ky, kx]
__device__ float g_S[N_SAMP];           // sum_j pk[n,j]
__device__ float g_bias[N_SAMP * CH];
__device__ float g_mean[N_SAMP * CH];
__device__ float g_rstd[N_SAMP * CH];

// ===========================================================================
// K1: fused independent work.
//   blocks [0, 8192)       : instance-norm stats per (n,c)
//   blocks [8192, 8256)    : bias GEMV (64 blocks x 8 channels, all samples)
//   blocks [8256, 8272)    : per-sample style conv -> d, S
// ===========================================================================
__global__ void __launch_bounds__(256) k1_kernel(
    const float* __restrict__ content,
    const float* __restrict__ style,
    const float* __restrict__ dw_w,
    const float* __restrict__ dw_b,
    const float* __restrict__ pk_w,
    const float* __restrict__ pk_b,
    const float* __restrict__ pb_w,
    const float* __restrict__ pb_b)
{
    __shared__ float sh[8704];          // 34 KB scratch, aliased per role
    int b   = blockIdx.x;
    int tid = threadIdx.x;
    int lane = tid & 31, warp = tid >> 5;

    // ---------------- stats ----------------
    if (b < N_SAMP * CH) {
        const float4* p = (const float4*)(content + (size_t)b * HW);
        float sum = 0.f, sq = 0.f;
        #pragma unroll
        for (int k = 0; k < 4; k++) {
            float4 v = p[tid + 256 * k];
            sum += v.x + v.y + v.z + v.w;
            sq  += v.x * v.x + v.y * v.y + v.z * v.z + v.w * v.w;
        }
        #pragma unroll
        for (int off = 16; off; off >>= 1) {
            sum += __shfl_down_sync(0xffffffffu, sum, off);
            sq  += __shfl_down_sync(0xffffffffu, sq,  off);
        }
        if (lane == 0) { sh[warp] = sum; sh[8 + warp] = sq; }
        __syncthreads();
        if (tid == 0) {
            float S = 0.f, Q = 0.f;
            #pragma unroll
            for (int w = 0; w < 8; w++) { S += sh[w]; Q += sh[8 + w]; }
            float mean = S * (1.f / HW);
            float var  = (Q - S * S * (1.f / HW)) * (1.f / (HW - 1));  // ddof=1
            g_mean[b] = mean;
            g_rstd[b] = rsqrtf(var + 1e-5f);
        }
        return;
    }
    b -= N_SAMP * CH;

    // ---------------- bias GEMV ----------------
    if (b < 64) {
        // sh = s_d[16][512]; each entry = mean over 4x4 style patch
        for (int idx = tid; idx < N_SAMP * 512; idx += 256) {
            const float4* p = (const float4*)(style + (size_t)idx * 16);
            float4 a = p[0], c4 = p[1], e = p[2], f = p[3];
            float s = a.x + a.y + a.z + a.w + c4.x + c4.y + c4.z + c4.w
                    + e.x + e.y + e.z + e.w + f.x + f.y + f.z + f.w;
            sh[idx] = s * (1.f / 16.f);
        }
        __syncthreads();
        int ch = b * 8 + warp;                       // output channel
        const float* row = pb_w + (size_t)ch * 512;
        float acc[N_SAMP];
        #pragma unroll
        for (int n = 0; n < N_SAMP; n++) acc[n] = 0.f;
        #pragma unroll
        for (int k = 0; k < 16; k++) {
            int c = lane + 32 * k;
            float wv = row[c];
            #pragma unroll
            for (int n = 0; n < N_SAMP; n++) acc[n] += wv * sh[n * 512 + c];
        }
        float bb = pb_b[ch];
        #pragma unroll
        for (int n = 0; n < N_SAMP; n++) {
            float a = acc[n];
            #pragma unroll
            for (int off = 16; off; off >>= 1)
                a += __shfl_down_sync(0xffffffffu, a, off);
            if (lane == 0) g_bias[n * 512 + ch] = a + bb;
        }
        return;
    }
    int n = b - 64;

    // ---------------- style conv (d) + S ----------------
    float* st = sh;          // [512][16]
    float* sd = sh + 8192;   // [512]
    const float4* sp = (const float4*)(style + (size_t)n * 8192);
    for (int i = tid; i < 2048; i += 256) ((float4*)st)[i] = sp[i];
    __syncthreads();
    for (int c = tid; c < 512; c += 256) {
        float a = 0.f;
        #pragma unroll
        for (int p = 0; p < 16; p++) a += st[c * 16 + p];
        sd[c] = a * (1.f / 16.f);
    }
    // warp j computes d[j, :, :] (9 positions), warp-parallel over channels
    {
        int j = warp;
        const float* wv = dw_w + (size_t)j * 2048;
        float bj = dw_b[j];
        for (int pos = 0; pos < 9; pos++) {
            int ky = pos / 3, kx = pos % 3;
            float acc = 0.f;
            #pragma unroll
            for (int k = 0; k < 16; k++) {
                int c = lane + 32 * k;
                const float* wc  = wv + c * 4;
                const float* stc = st + c * 16 + ky * 4 + kx;
                acc += wc[0] * stc[0] + wc[1] * stc[1]
                     + wc[2] * stc[4] + wc[3] * stc[5];
            }
            #pragma unroll
            for (int off = 16; off; off >>= 1)
                acc += __shfl_down_sync(0xffffffffu, acc, off);
            if (lane == 0) {
                float v = acc + bj;
                g_d[n * 72 + j * 9 + pos] = v >= 0.f ? v : 0.01f * v;
            }
        }
    }
    __syncthreads();
    if (warp == 0) {
        float acc = 0.f;
        #pragma unroll
        for (int k = 0; k < 16; k++) {
            int c = lane + 32 * k;
            float ws = 0.f;
            #pragma unroll
            for (int j = 0; j < 8; j++) ws += pk_w[j * 512 + c];
            acc += sd[c] * ws;
        }
        #pragma unroll
        for (int off = 16; off; off >>= 1)
            acc += __shfl_down_sync(0xffffffffu, acc, off);
        if (lane == 0) {
            float bsum = 0.f;
            #pragma unroll
            for (int j = 0; j < 8; j++) bsum += pk_b[j];
            g_S[n] = acc + bsum;
        }
    }
}

// ===========================================================================
// K2: fused group conv + pointwise collapse + instance norm + multiply.
// Grid (2 tiles, 64 groups, 16 samples) x 256 threads. TILE_H=32, dyn smem.
// ===========================================================================
#define TILE_H 32
#define SROWS 34
#define SCOLS 66
#define STILE (8 * SROWS * SCOLS)      // 17952 floats = 71808 B

__global__ void __launch_bounds__(256) main_kernel(
    const float* __restrict__ content, float* __restrict__ out)
{
    extern __shared__ float s[];       // [8][SROWS][SCOLS]
    __shared__ float fd[72];
    __shared__ float fb[8], fm[8], fr[8];
    __shared__ float fS;

    int tile = blockIdx.x;   // 0..1
    int g    = blockIdx.y;   // 0..63
    int n    = blockIdx.z;   // 0..15
    int tid  = threadIdx.x;

    int cbase = n * 512 + g * 8;
    if (tid < 72)       fd[tid] = g_d[n * 72 + tid];
    else if (tid < 80)  fb[tid - 72] = g_bias[cbase + tid - 72];
    else if (tid < 88)  fm[tid - 80] = g_mean[cbase + tid - 80];
    else if (tid < 96)  fr[tid - 88] = g_rstd[cbase + tid - 88];
    else if (tid == 96) fS = g_S[n];

    const float* base = content + (size_t)cbase * HW;
    int row0 = tile * TILE_H;

    // interior columns: float4 loads (8 ch x 34 rows x 16 float4)
    for (int idx = tid; idx < 8 * SROWS * 16; idx += 256) {
        int r = idx >> 4;            // channel-row 0..271
        int q = idx & 15;
        int j  = r / SROWS;
        int lr = r % SROWS;
        int gr = row0 + lr - 1;
        gr = gr < 0 ? -gr : (gr >= H ? 2 * H - 2 - gr : gr);
        float4 v = *(const float4*)(base + (size_t)j * HW + gr * W + 4 * q);
        float* dst = s + j * (SROWS * SCOLS) + lr * SCOLS + 1 + 4 * q;
        dst[0] = v.x; dst[1] = v.y; dst[2] = v.z; dst[3] = v.w;
    }
    // border columns (reflect)
    for (int idx = tid; idx < 8 * SROWS * 2; idx += 256) {
        int r = idx >> 1;
        int side = idx & 1;
        int j  = r / SROWS;
        int lr = r % SROWS;
        int gr = row0 + lr - 1;
        gr = gr < 0 ? -gr : (gr >= H ? 2 * H - 2 - gr : gr);
        int lc = side ? 65 : 0;
        int gc = side ? 62 : 1;      // reflect of 64 and -1
        s[j * (SROWS * SCOLS) + lr * SCOLS + lc] = base[(size_t)j * HW + gr * W + gc];
    }
    __syncthreads();

    int r2 = tid >> 4;               // 0..15 -> row pair
    int w0 = (tid & 15) * 4;         // col group
    int h0 = 2 * r2;                 // rows h0, h0+1 in tile

    float D0[4] = {0.f, 0.f, 0.f, 0.f};
    float D1[4] = {0.f, 0.f, 0.f, 0.f};

    #pragma unroll
    for (int j = 0; j < 8; j++) {
        const float* sj = s + j * (SROWS * SCOLS);
        const float* fj = fd + j * 9;
        #pragma unroll
        for (int rr = 0; rr < 4; rr++) {
            const float* rowp = sj + (h0 + rr) * SCOLS + w0;
            float v0 = rowp[0], v1 = rowp[1], v2 = rowp[2];
            float v3 = rowp[3], v4 = rowp[4], v5 = rowp[5];
            if (rr < 3) {
                float a = fj[rr * 3], b2 = fj[rr * 3 + 1], c = fj[rr * 3 + 2];
                D0[0] += a * v0 + b2 * v1 + c * v2;
                D0[1] += a * v1 + b2 * v2 + c * v3;
                D0[2] += a * v2 + b2 * v3 + c * v4;
                D0[3] += a * v3 + b2 * v4 + c * v5;
            }
            if (rr >= 1) {
                int kr = rr - 1;
                float a = fj[kr * 3], b2 = fj[kr * 3 + 1], c = fj[kr * 3 + 2];
                D1[0] += a * v0 + b2 * v1 + c * v2;
                D1[1] += a * v1 + b2 * v2 + c * v3;
                D1[2] += a * v2 + b2 * v3 + c * v4;
                D1[3] += a * v3 + b2 * v4 + c * v5;
            }
        }
    }

    float S = fS;
    float* obase = out + (size_t)cbase * HW + (row0 + h0) * W + w0;

    #pragma unroll
    for (int o = 0; o < 8; o++) {
        const float* so = s + o * (SROWS * SCOLS);
        float mo = fm[o], ro = fr[o], bo = fb[o];
        float4 r0v, r1v;
        {
            const float* cen = so + (h0 + 1) * SCOLS + w0 + 1;
            float p0 = D0[0] * S + bo, p1 = D0[1] * S + bo;
            float p2 = D0[2] * S + bo, p3 = D0[3] * S + bo;
            p0 = p0 >= 0.f ? p0 : 0.01f * p0;
            p1 = p1 >= 0.f ? p1 : 0.01f * p1;
            p2 = p2 >= 0.f ? p2 : 0.01f * p2;
            p3 = p3 >= 0.f ? p3 : 0.01f * p3;
            r0v.x = (cen[0] - mo) * ro * p0;
            r0v.y = (cen[1] - mo) * ro * p1;
            r0v.z = (cen[2] - mo) * ro * p2;
            r0v.w = (cen[3] - mo) * ro * p3;
        }
        {
            const float* cen = so + (h0 + 2) * SCOLS + w0 + 1;
            float p0 = D1[0] * S + bo, p1 = D1[1] * S + bo;
            float p2 = D1[2] * S + bo, p3 = D1[3] * S + bo;
            p0 = p0 >= 0.f ? p0 : 0.01f * p0;
            p1 = p1 >= 0.f ? p1 : 0.01f * p1;
            p2 = p2 >= 0.f ? p2 : 0.01f * p2;
            p3 = p3 >= 0.f ? p3 : 0.01f * p3;
            r1v.x = (cen[0] - mo) * ro * p0;
            r1v.y = (cen[1] - mo) * ro * p1;
            r1v.z = (cen[2] - mo) * ro * p2;
            r1v.w = (cen[3] - mo) * ro * p3;
        }
        *(float4*)(obase + (size_t)o * HW)     = r0v;
        *(float4*)(obase + (size_t)o * HW + W) = r1v;
    }
}

// ===========================================================================
extern "C" void kernel_launch(void* const* d_in, const int* in_sizes, int n_in,
                              void* d_out, int out_size)
{
    const float* style   = (const float*)d_in[0];
    const float* content = (const float*)d_in[1];
    const float* dw_w    = (const float*)d_in[2];
    const float* dw_b    = (const float*)d_in[3];
    const float* pk_w    = (const float*)d_in[4];
    const float* pk_b    = (const float*)d_in[5];
    const float* pb_w    = (const float*)d_in[6];
    const float* pb_b    = (const float*)d_in[7];
    float* out = (float*)d_out;

    static bool attr_set = false;
    if (!attr_set) {
        cudaFuncSetAttribute(main_kernel,
                             cudaFuncAttributeMaxDynamicSharedMemorySize,
                             STILE * sizeof(float));
        attr_set = true;
    }

    k1_kernel<<<N_SAMP * CH + 64 + N_SAMP, 256>>>(
        content, style, dw_w, dw_b, pk_w, pk_b, pb_w, pb_b);
    main_kernel<<<dim3(2, NG, N_SAMP), 256, STILE * sizeof(float)>>>(content, out);
}

// round 4
// speedup vs baseline: 2.5495x; 1.7935x over previous
#include <cuda_runtime.h>
#include <math.h>

#define CH 512
#define NG 64
#define N_SAMP 16
#define H 64
#define W 64
#define HW 4096

#define SROWS 66
#define SCOLS 66
#define CHTILE (SROWS * SCOLS)          // 4356 floats per channel
#define STILE  (8 * CHTILE)             // 34848 floats = 139392 B

__device__ float g_d[N_SAMP * 72];      // leaky(d)[n, j, ky, kx]
__device__ float g_S[N_SAMP];           // sum_j pk[n,j]
__device__ float g_bias[N_SAMP * CH];

// ===========================================================================
// Prep: blocks [0,64) bias GEMV; blocks [64,80) per-sample style conv + S.
// ===========================================================================
__global__ void __launch_bounds__(256) prep_kernel(
    const float* __restrict__ style,
    const float* __restrict__ dw_w,
    const float* __restrict__ dw_b,
    const float* __restrict__ pk_w,
    const float* __restrict__ pk_b,
    const float* __restrict__ pb_w,
    const float* __restrict__ pb_b)
{
    __shared__ float sh[8704];          // 34 KB scratch
    int b   = blockIdx.x;
    int tid = threadIdx.x;
    int lane = tid & 31, warp = tid >> 5;

    // ---------------- bias GEMV ----------------
    if (b < 64) {
        // sh = s_d[16][512]
        for (int idx = tid; idx < N_SAMP * 512; idx += 256) {
            const float4* p = (const float4*)(style + (size_t)idx * 16);
            float4 a = p[0], c4 = p[1], e = p[2], f = p[3];
            float s = a.x + a.y + a.z + a.w + c4.x + c4.y + c4.z + c4.w
                    + e.x + e.y + e.z + e.w + f.x + f.y + f.z + f.w;
            sh[idx] = s * (1.f / 16.f);
        }
        __syncthreads();
        int ch = b * 8 + warp;
        const float* row = pb_w + (size_t)ch * 512;
        float acc[N_SAMP];
        #pragma unroll
        for (int n = 0; n < N_SAMP; n++) acc[n] = 0.f;
        #pragma unroll
        for (int k = 0; k < 16; k++) {
            int c = lane + 32 * k;
            float wv = row[c];
            #pragma unroll
            for (int n = 0; n < N_SAMP; n++) acc[n] += wv * sh[n * 512 + c];
        }
        float bb = pb_b[ch];
        #pragma unroll
        for (int n = 0; n < N_SAMP; n++) {
            float a = acc[n];
            #pragma unroll
            for (int off = 16; off; off >>= 1)
                a += __shfl_down_sync(0xffffffffu, a, off);
            if (lane == 0) g_bias[n * 512 + ch] = a + bb;
        }
        return;
    }
    int n = b - 64;

    // ---------------- style conv (d) + S ----------------
    float* st = sh;          // [512][16]
    float* sd = sh + 8192;   // [512]
    const float4* sp = (const float4*)(style + (size_t)n * 8192);
    for (int i = tid; i < 2048; i += 256) ((float4*)st)[i] = sp[i];
    __syncthreads();
    for (int c = tid; c < 512; c += 256) {
        float a = 0.f;
        #pragma unroll
        for (int p = 0; p < 16; p++) a += st[c * 16 + p];
        sd[c] = a * (1.f / 16.f);
    }
    {
        int j = warp;
        const float* wv = dw_w + (size_t)j * 2048;
        float bj = dw_b[j];
        for (int pos = 0; pos < 9; pos++) {
            int ky = pos / 3, kx = pos % 3;
            float acc = 0.f;
            #pragma unroll
            for (int k = 0; k < 16; k++) {
                int c = lane + 32 * k;
                const float* wc  = wv + c * 4;
                const float* stc = st + c * 16 + ky * 4 + kx;
                acc += wc[0] * stc[0] + wc[1] * stc[1]
                     + wc[2] * stc[4] + wc[3] * stc[5];
            }
            #pragma unroll
            for (int off = 16; off; off >>= 1)
                acc += __shfl_down_sync(0xffffffffu, acc, off);
            if (lane == 0) {
                float v = acc + bj;
                g_d[n * 72 + j * 9 + pos] = v >= 0.f ? v : 0.01f * v;
            }
        }
    }
    __syncthreads();
    if (warp == 0) {
        float acc = 0.f;
        #pragma unroll
        for (int k = 0; k < 16; k++) {
            int c = lane + 32 * k;
            float ws = 0.f;
            #pragma unroll
            for (int j = 0; j < 8; j++) ws += pk_w[j * 512 + c];
            acc += sd[c] * ws;
        }
        #pragma unroll
        for (int off = 16; off; off >>= 1)
            acc += __shfl_down_sync(0xffffffffu, acc, off);
        if (lane == 0) {
            float bsum = 0.f;
            #pragma unroll
            for (int j = 0; j < 8; j++) bsum += pk_b[j];
            g_S[n] = acc + bsum;
        }
    }
}

// ===========================================================================
// Main: one block per (group, sample) holding the FULL 8x(66x66) tile.
// Stats accumulated in registers during the load -> content read ONCE.
// Grid (64, 16) x 512 threads.
// ===========================================================================
__global__ void __launch_bounds__(512) main_kernel(
    const float* __restrict__ content, float* __restrict__ out)
{
    extern __shared__ float s[];        // [8][SROWS][SCOLS]
    __shared__ float fd[72];
    __shared__ float fb[8], fm[8], fr[8];
    __shared__ float red[32];
    __shared__ float fS_sh;

    int g = blockIdx.x;                 // 0..63
    int n = blockIdx.y;                 // 0..15
    int tid = threadIdx.x;
    int lane = tid & 31, warp = tid >> 5;
    int cbase = n * 512 + g * 8;

    if (tid < 72)       fd[tid] = g_d[n * 72 + tid];
    else if (tid < 80)  fb[tid - 72] = g_bias[cbase + tid - 72];
    else if (tid == 80) fS_sh = g_S[n];

    // ---- load full channel-group with reflect halo; warp pair per channel ----
    int c    = warp >> 1;               // channel 0..7
    int half = warp & 1;                // row-half
    const float* bc = content + (size_t)(cbase + c) * HW;
    float* sc = s + c * CHTILE;
    float sum = 0.f, sq = 0.f;
    int sub = lane >> 4, q = lane & 15; // two rows per iteration
    #pragma unroll
    for (int i = 0; i < 17; i++) {
        int rr = 2 * i + sub;
        if (rr < 33) {
            int lr = half * 33 + rr;                      // smem row 0..65
            int gr = (lr == 0) ? 1 : (lr == 65 ? 62 : lr - 1);  // reflect
            float4 v = *(const float4*)(bc + gr * W + 4 * q);
            float* dst = sc + lr * SCOLS + 1 + 4 * q;
            dst[0] = v.x; dst[1] = v.y; dst[2] = v.z; dst[3] = v.w;
            if (lr >= 1 && lr <= 64) {                    // interior only
                sum += v.x + v.y + v.z + v.w;
                sq  += v.x * v.x + v.y * v.y + v.z * v.z + v.w * v.w;
            }
        }
    }
    // border columns (reflect of cols -1 and 64)
    for (int idx = tid; idx < 8 * SROWS; idx += 512) {
        int c2 = idx / SROWS, lr = idx % SROWS;
        int gr = (lr == 0) ? 1 : (lr == 65 ? 62 : lr - 1);
        const float* b2 = content + (size_t)(cbase + c2) * HW + gr * W;
        float* row = s + c2 * CHTILE + lr * SCOLS;
        row[0]  = b2[1];
        row[65] = b2[62];
    }
    // ---- stats reduce ----
    #pragma unroll
    for (int off = 16; off; off >>= 1) {
        sum += __shfl_down_sync(0xffffffffu, sum, off);
        sq  += __shfl_down_sync(0xffffffffu, sq,  off);
    }
    if (lane == 0) { red[warp] = sum; red[16 + warp] = sq; }
    __syncthreads();
    if (tid < 8) {
        float S = red[2 * tid] + red[2 * tid + 1];
        float Q = red[16 + 2 * tid] + red[16 + 2 * tid + 1];
        float mean = S * (1.f / HW);
        float var  = (Q - S * S * (1.f / HW)) * (1.f / (HW - 1));  // ddof=1
        fm[tid] = mean;
        fr[tid] = rsqrtf(var + 1e-5f);
    }
    __syncthreads();

    // ---- conv: 2 rows x 4 cols per thread ----
    int r2 = tid >> 4;                  // 0..31
    int w0 = (tid & 15) * 4;            // 0..60
    int h0 = 2 * r2;                    // output rows h0, h0+1

    float D0[4] = {0.f, 0.f, 0.f, 0.f};
    float D1[4] = {0.f, 0.f, 0.f, 0.f};

    #pragma unroll
    for (int j = 0; j < 8; j++) {
        const float* sj = s + j * CHTILE;
        const float* fj = fd + j * 9;
        #pragma unroll
        for (int rr = 0; rr < 4; rr++) {
            const float* rowp = sj + (h0 + rr) * SCOLS + w0;
            float v0 = rowp[0], v1 = rowp[1], v2 = rowp[2];
            float v3 = rowp[3], v4 = rowp[4], v5 = rowp[5];
            if (rr < 3) {
                float a = fj[rr * 3], b2 = fj[rr * 3 + 1], cc = fj[rr * 3 + 2];
                D0[0] += a * v0 + b2 * v1 + cc * v2;
                D0[1] += a * v1 + b2 * v2 + cc * v3;
                D0[2] += a * v2 + b2 * v3 + cc * v4;
                D0[3] += a * v3 + b2 * v4 + cc * v5;
            }
            if (rr >= 1) {
                int kr = rr - 1;
                float a = fj[kr * 3], b2 = fj[kr * 3 + 1], cc = fj[kr * 3 + 2];
                D1[0] += a * v0 + b2 * v1 + cc * v2;
                D1[1] += a * v1 + b2 * v2 + cc * v3;
                D1[2] += a * v2 + b2 * v3 + cc * v4;
                D1[3] += a * v3 + b2 * v4 + cc * v5;
            }
        }
    }

    float S = fS_sh;
    float* obase = out + (size_t)cbase * HW + h0 * W + w0;

    #pragma unroll
    for (int o = 0; o < 8; o++) {
        const float* so = s + o * CHTILE;
        float mo = fm[o], ro = fr[o], bo = fb[o];
        float4 r0v, r1v;
        {
            const float* cen = so + (h0 + 1) * SCOLS + w0 + 1;
            float p0 = D0[0] * S + bo, p1 = D0[1] * S + bo;
            float p2 = D0[2] * S + bo, p3 = D0[3] * S + bo;
            p0 = p0 >= 0.f ? p0 : 0.01f * p0;
            p1 = p1 >= 0.f ? p1 : 0.01f * p1;
            p2 = p2 >= 0.f ? p2 : 0.01f * p2;
            p3 = p3 >= 0.f ? p3 : 0.01f * p3;
            r0v.x = (cen[0] - mo) * ro * p0;
            r0v.y = (cen[1] - mo) * ro * p1;
            r0v.z = (cen[2] - mo) * ro * p2;
            r0v.w = (cen[3] - mo) * ro * p3;
        }
        {
            const float* cen = so + (h0 + 2) * SCOLS + w0 + 1;
            float p0 = D1[0] * S + bo, p1 = D1[1] * S + bo;
            float p2 = D1[2] * S + bo, p3 = D1[3] * S + bo;
            p0 = p0 >= 0.f ? p0 : 0.01f * p0;
            p1 = p1 >= 0.f ? p1 : 0.01f * p1;
            p2 = p2 >= 0.f ? p2 : 0.01f * p2;
            p3 = p3 >= 0.f ? p3 : 0.01f * p3;
            r1v.x = (cen[0] - mo) * ro * p0;
            r1v.y = (cen[1] - mo) * ro * p1;
            r1v.z = (cen[2] - mo) * ro * p2;
            r1v.w = (cen[3] - mo) * ro * p3;
        }
        *(float4*)(obase + (size_t)o * HW)     = r0v;
        *(float4*)(obase + (size_t)o * HW + W) = r1v;
    }
}

// ===========================================================================
extern "C" void kernel_launch(void* const* d_in, const int* in_sizes, int n_in,
                              void* d_out, int out_size)
{
    const float* style   = (const float*)d_in[0];
    const float* content = (const float*)d_in[1];
    const float* dw_w    = (const float*)d_in[2];
    const float* dw_b    = (const float*)d_in[3];
    const float* pk_w    = (const float*)d_in[4];
    const float* pk_b    = (const float*)d_in[5];
    const float* pb_w    = (const float*)d_in[6];
    const float* pb_b    = (const float*)d_in[7];
    float* out = (float*)d_out;

    static bool attr_set = false;
    if (!attr_set) {
        cudaFuncSetAttribute(main_kernel,
                             cudaFuncAttributeMaxDynamicSharedMemorySize,
                             STILE * sizeof(float));
        attr_set = true;
    }

    prep_kernel<<<80, 256>>>(style, dw_w, dw_b, pk_w, pk_b, pb_w, pb_b);
    main_kernel<<<dim3(NG, N_SAMP), 512, STILE * sizeof(float)>>>(content, out);
}